// round 6
// baseline (speedup 1.0000x reference)
#include <cuda_runtime.h>

#define BATCH 2
#define LSEQ  16384
#define BLR   (BATCH*LSEQ)   // 32768 rows
#define DM    60
#define DI    120
#define DS    16
#define NCH   64
#define SCH   (LSEQ/NCH)

// ------------------------- scratch -------------------------
__device__ float g_hn[BLR*DM];
__device__ float g_xz[BLR*2*DI];
__device__ float g_xc[BLR*DI];
__device__ float g_xdb[BLR*36];
__device__ float g_delta[BLR*DI];
__device__ float g_u[BLR*DI];
__device__ float g_y[BLR*DI];
__device__ float g_h[BLR*DM];
__device__ float g_P [NCH*BATCH*DI*DS];
__device__ float g_Hc[NCH*BATCH*DI*DS];
__device__ float g_hinit[NCH*BATCH*DI*DS];
__device__ float g_wt_in [2*DM*2*DI];   // [60][240] per layer
__device__ float g_wt_xp [2*DI*36];     // [120][36]
__device__ float g_wt_out[2*DI*DM];     // [120][60]
__device__ float g_wT    [9*DM*DM];     // [tap][ci][co]

__device__ __forceinline__ float siluf(float x) { return x / (1.f + __expf(-x)); }

// ------------------------- weight prep -------------------------
__global__ void prep_weights(const float* __restrict__ in_w, const float* __restrict__ xp_w,
                             const float* __restrict__ out_w, const float* __restrict__ c2w) {
    int t = blockIdx.y;
    int i = blockIdx.x * 256 + threadIdx.x;
    if (t < 2) {
        if (i < 240 * 60) {
            int n = i / 60, k = i - n * 60;
            g_wt_in[t * 60 * 240 + k * 240 + n] = in_w[t * 240 * 60 + n * 60 + k];
        }
    } else if (t < 4) {
        int l = t - 2;
        if (i < 36 * 120) {
            int n = i / 120, k = i - n * 120;
            g_wt_xp[l * 120 * 36 + k * 36 + n] = xp_w[l * 36 * 120 + n * 120 + k];
        }
    } else if (t < 6) {
        int l = t - 4;
        if (i < 60 * 120) {
            int n = i / 120, k = i - n * 120;
            g_wt_out[l * 120 * 60 + k * 60 + n] = out_w[l * 60 * 120 + n * 120 + k];
        }
    } else {
        if (i < 9 * 60 * 60) {
            int tap = i / 3600;
            int r = i - tap * 3600;
            int ci = r / 60, co = r - ci * 60;
            g_wT[i] = c2w[(co * 60 + ci) * 9 + tap];
        }
    }
}

// ------------------------- LayerNorm -------------------------
__global__ void ln_kernel(const float* __restrict__ in, const float* __restrict__ w,
                          const float* __restrict__ b) {
    int row  = blockIdx.x * 8 + (threadIdx.x >> 5);
    int lane = threadIdx.x & 31;
    const float* r = in + (size_t)row * DM;
    float v0 = r[lane];
    float v1 = (lane + 32 < DM) ? r[lane + 32] : 0.f;
    float s = v0 + v1;
#pragma unroll
    for (int o = 16; o; o >>= 1) s += __shfl_xor_sync(0xffffffffu, s, o);
    float mu = s * (1.f / DM);
    float d0 = v0 - mu;
    float d1 = (lane + 32 < DM) ? (v1 - mu) : 0.f;
    float q = d0 * d0 + d1 * d1;
#pragma unroll
    for (int o = 16; o; o >>= 1) q += __shfl_xor_sync(0xffffffffu, q, o);
    float rstd = rsqrtf(q * (1.f / DM) + 1e-5f);
    float* op = g_hn + (size_t)row * DM;
    op[lane] = d0 * rstd * w[lane] + b[lane];
    if (lane + 32 < DM) op[lane + 32] = d1 * rstd * w[lane + 32] + b[lane + 32];
}

// ------------------------- GEMM 128x64, 8x4 microtile -------------------------
// C[m,n] = sum_k A[m,k]*WT[k,n], K multiple of 60
__global__ __launch_bounds__(256) void gemm128(const float* __restrict__ A,
                                               const float* __restrict__ WT,
                                               float* __restrict__ C, int N, int K) {
    __shared__ float Asr[128][60];
    __shared__ float Ws[60][64];
    int m0 = blockIdx.x * 128;
    int n0 = blockIdx.y * 64;
    int tid = threadIdx.x;
    int r0 = (tid >> 4) * 8;
    int c0 = (tid & 15) * 4;
    float acc[8][4];
#pragma unroll
    for (int i = 0; i < 8; i++)
#pragma unroll
        for (int j = 0; j < 4; j++) acc[i][j] = 0.f;

    for (int kc = 0; kc < K; kc += 60) {
        for (int i = tid; i < 1920; i += 256) {           // 128*15 float4
            int r = i / 15, kk = (i - r * 15) * 4;
            *(float4*)&Asr[r][kk] = *(const float4*)&A[(size_t)(m0 + r) * K + kc + kk];
        }
        for (int i = tid; i < 960; i += 256) {            // 60*16 float4
            int k = i >> 4, n = (i & 15) * 4;
            int nn = n0 + n;
            float4 w;
            const float* wp = WT + (size_t)(kc + k) * N + nn;
            w.x = (nn + 0 < N) ? wp[0] : 0.f;
            w.y = (nn + 1 < N) ? wp[1] : 0.f;
            w.z = (nn + 2 < N) ? wp[2] : 0.f;
            w.w = (nn + 3 < N) ? wp[3] : 0.f;
            *(float4*)&Ws[k][n] = w;
        }
        __syncthreads();
#pragma unroll 6
        for (int k = 0; k < 60; k++) {
            float4 w4 = *(const float4*)&Ws[k][c0];
            float a[8];
#pragma unroll
            for (int i = 0; i < 8; i++) a[i] = Asr[r0 + i][k];
#pragma unroll
            for (int i = 0; i < 8; i++) {
                acc[i][0] = fmaf(a[i], w4.x, acc[i][0]);
                acc[i][1] = fmaf(a[i], w4.y, acc[i][1]);
                acc[i][2] = fmaf(a[i], w4.z, acc[i][2]);
                acc[i][3] = fmaf(a[i], w4.w, acc[i][3]);
            }
        }
        __syncthreads();
    }
#pragma unroll
    for (int i = 0; i < 8; i++) {
        int m = m0 + r0 + i;
        int nn = n0 + c0;
        if (nn + 3 < N) {
            *(float4*)&C[(size_t)m * N + nn] = make_float4(acc[i][0], acc[i][1], acc[i][2], acc[i][3]);
        } else {
#pragma unroll
            for (int j = 0; j < 4; j++)
                if (nn + j < N) C[(size_t)m * N + nn + j] = acc[i][j];
        }
    }
}

// ------------------------- x_proj GEMM: 128x36 exact, 288 threads, 4x4 ----------
__global__ __launch_bounds__(288) void gemm_xp(const float* __restrict__ A,
                                               const float* __restrict__ WT) {
    __shared__ float Asr[128][60];
    __shared__ float Ws[60][36];
    int m0 = blockIdx.x * 128;
    int tid = threadIdx.x;
    int r0 = (tid / 9) * 4;
    int c0 = (tid % 9) * 4;
    float acc[4][4];
#pragma unroll
    for (int i = 0; i < 4; i++)
#pragma unroll
        for (int j = 0; j < 4; j++) acc[i][j] = 0.f;

    for (int kc = 0; kc < DI; kc += 60) {
        for (int i = tid; i < 1920; i += 288) {
            int r = i / 15, kk = (i - r * 15) * 4;
            *(float4*)&Asr[r][kk] = *(const float4*)&A[(size_t)(m0 + r) * DI + kc + kk];
        }
        for (int i = tid; i < 540; i += 288) {            // 60*9 float4
            int k = i / 9, n = (i - k * 9) * 4;
            *(float4*)&Ws[k][n] = *(const float4*)&WT[(size_t)(kc + k) * 36 + n];
        }
        __syncthreads();
#pragma unroll 6
        for (int k = 0; k < 60; k++) {
            float4 w4 = *(const float4*)&Ws[k][c0];
            float a0 = Asr[r0 + 0][k], a1 = Asr[r0 + 1][k];
            float a2 = Asr[r0 + 2][k], a3 = Asr[r0 + 3][k];
            acc[0][0] = fmaf(a0, w4.x, acc[0][0]); acc[0][1] = fmaf(a0, w4.y, acc[0][1]);
            acc[0][2] = fmaf(a0, w4.z, acc[0][2]); acc[0][3] = fmaf(a0, w4.w, acc[0][3]);
            acc[1][0] = fmaf(a1, w4.x, acc[1][0]); acc[1][1] = fmaf(a1, w4.y, acc[1][1]);
            acc[1][2] = fmaf(a1, w4.z, acc[1][2]); acc[1][3] = fmaf(a1, w4.w, acc[1][3]);
            acc[2][0] = fmaf(a2, w4.x, acc[2][0]); acc[2][1] = fmaf(a2, w4.y, acc[2][1]);
            acc[2][2] = fmaf(a2, w4.z, acc[2][2]); acc[2][3] = fmaf(a2, w4.w, acc[2][3]);
            acc[3][0] = fmaf(a3, w4.x, acc[3][0]); acc[3][1] = fmaf(a3, w4.y, acc[3][1]);
            acc[3][2] = fmaf(a3, w4.z, acc[3][2]); acc[3][3] = fmaf(a3, w4.w, acc[3][3]);
        }
        __syncthreads();
    }
#pragma unroll
    for (int i = 0; i < 4; i++) {
        int m = m0 + r0 + i;
        *(float4*)&g_xdb[(size_t)m * 36 + c0] = make_float4(acc[i][0], acc[i][1], acc[i][2], acc[i][3]);
    }
}

// ------------------------- out_proj 128x64, gated fill -------------------------
__global__ __launch_bounds__(256) void gemm_out_gated(const float* __restrict__ WT,
                                                      const float* __restrict__ Dvec) {
    __shared__ float Asr[128][60];
    __shared__ float Ws[60][64];
    int m0 = blockIdx.x * 128;
    int tid = threadIdx.x;
    int r0 = (tid >> 4) * 8;
    int c0 = (tid & 15) * 4;
    float acc[8][4];
#pragma unroll
    for (int i = 0; i < 8; i++)
#pragma unroll
        for (int j = 0; j < 4; j++) acc[i][j] = 0.f;

    for (int kc = 0; kc < DI; kc += 60) {
        for (int i = tid; i < 128 * 60; i += 256) {
            int r = i / 60, k = i - r * 60;
            int m = m0 + r;
            int e = kc + k;
            float yv  = g_y [(size_t)m * DI + e];
            float xcv = g_xc[(size_t)m * DI + e];
            float zv  = g_xz[(size_t)m * (2 * DI) + DI + e];
            Asr[r][k] = (yv + __ldg(Dvec + e) * xcv) * siluf(zv);
        }
        for (int i = tid; i < 960; i += 256) {
            int k = i >> 4, n = (i & 15) * 4;
            float4 w;
            const float* wp = WT + (size_t)(kc + k) * DM + n;
            w.x = (n + 0 < DM) ? wp[0] : 0.f;
            w.y = (n + 1 < DM) ? wp[1] : 0.f;
            w.z = (n + 2 < DM) ? wp[2] : 0.f;
            w.w = (n + 3 < DM) ? wp[3] : 0.f;
            *(float4*)&Ws[k][n] = w;
        }
        __syncthreads();
#pragma unroll 6
        for (int k = 0; k < 60; k++) {
            float4 w4 = *(const float4*)&Ws[k][c0];
            float a[8];
#pragma unroll
            for (int i = 0; i < 8; i++) a[i] = Asr[r0 + i][k];
#pragma unroll
            for (int i = 0; i < 8; i++) {
                acc[i][0] = fmaf(a[i], w4.x, acc[i][0]);
                acc[i][1] = fmaf(a[i], w4.y, acc[i][1]);
                acc[i][2] = fmaf(a[i], w4.z, acc[i][2]);
                acc[i][3] = fmaf(a[i], w4.w, acc[i][3]);
            }
        }
        __syncthreads();
    }
#pragma unroll
    for (int i = 0; i < 8; i++) {
        int m = m0 + r0 + i;
#pragma unroll
        for (int j = 0; j < 4; j++) {
            int n = c0 + j;
            if (n < DM) g_h[(size_t)m * DM + n] = acc[i][j];
        }
    }
}

// ------------------------- conv1d + SiLU -------------------------
__global__ void conv1d_silu(const float* __restrict__ cw, const float* __restrict__ cb) {
    int idx = blockIdx.x * 256 + threadIdx.x;
    if (idx >= BLR * (DI / 4)) return;
    int m = idx / (DI / 4);
    int d = (idx - m * (DI / 4)) * 4;
    int l = m & (LSEQ - 1);
    const float4* base = (const float4*)(g_xz + (size_t)m * (2 * DI) + d);
    float4 zero = make_float4(0.f, 0.f, 0.f, 0.f);
    float4 x0 = __ldg(base);
    float4 x1 = (l >= 1) ? __ldg(base - (2 * DI) / 4) : zero;
    float4 x2 = (l >= 2) ? __ldg(base - 2 * (2 * DI) / 4) : zero;
    float4 x3 = (l >= 3) ? __ldg(base - 3 * (2 * DI) / 4) : zero;
    float4 wa = __ldg((const float4*)(cw + (d + 0) * 4));
    float4 wb = __ldg((const float4*)(cw + (d + 1) * 4));
    float4 wc = __ldg((const float4*)(cw + (d + 2) * 4));
    float4 wd = __ldg((const float4*)(cw + (d + 3) * 4));
    float4 bb = __ldg((const float4*)(cb + d));
    float4 o;
    o.x = siluf(bb.x + x0.x * wa.w + x1.x * wa.z + x2.x * wa.y + x3.x * wa.x);
    o.y = siluf(bb.y + x0.y * wb.w + x1.y * wb.z + x2.y * wb.y + x3.y * wb.x);
    o.z = siluf(bb.z + x0.z * wc.w + x1.z * wc.z + x2.z * wc.y + x3.z * wc.x);
    o.w = siluf(bb.w + x0.w * wd.w + x1.w * wd.z + x2.w * wd.y + x3.w * wd.x);
    *(float4*)(g_xc + (size_t)m * DI + d) = o;
}

// ------------------------- delta -------------------------
__global__ void delta_kernel(const float* __restrict__ dtw, const float* __restrict__ dtb) {
    int idx = blockIdx.x * 256 + threadIdx.x;
    if (idx >= BLR * (DI / 4)) return;
    int m = idx / (DI / 4);
    int d = (idx - m * (DI / 4)) * 4;
    float4 xr = __ldg((const float4*)(g_xdb + (size_t)m * 36));
    float4 w0 = __ldg((const float4*)(dtw + (d + 0) * 4));
    float4 w1 = __ldg((const float4*)(dtw + (d + 1) * 4));
    float4 w2 = __ldg((const float4*)(dtw + (d + 2) * 4));
    float4 w3 = __ldg((const float4*)(dtw + (d + 3) * 4));
    float4 bb = __ldg((const float4*)(dtb + d));
    float s0 = bb.x + xr.x * w0.x + xr.y * w0.y + xr.z * w0.z + xr.w * w0.w;
    float s1 = bb.y + xr.x * w1.x + xr.y * w1.y + xr.z * w1.z + xr.w * w1.w;
    float s2 = bb.z + xr.x * w2.x + xr.y * w2.y + xr.z * w2.z + xr.w * w2.w;
    float s3 = bb.w + xr.x * w3.x + xr.y * w3.y + xr.z * w3.z + xr.w * w3.w;
    float4 dl;
    dl.x = (s0 > 20.f) ? s0 : log1pf(__expf(s0));
    dl.y = (s1 > 20.f) ? s1 : log1pf(__expf(s1));
    dl.z = (s2 > 20.f) ? s2 : log1pf(__expf(s2));
    dl.w = (s3 > 20.f) ? s3 : log1pf(__expf(s3));
    float4 xc = __ldg((const float4*)(g_xc + (size_t)m * DI + d));
    float4 uu = make_float4(dl.x * xc.x, dl.y * xc.y, dl.z * xc.z, dl.w * xc.w);
    *(float4*)(g_delta + (size_t)m * DI + d) = dl;
    *(float4*)(g_u + (size_t)m * DI + d) = uu;
}

// ------------------------- chunked selective scan -------------------------
__global__ __launch_bounds__(128) void scan_phase1(const float* __restrict__ A_log) {
    int w = blockIdx.x * 4 + (threadIdx.x >> 5);
    int lane = threadIdx.x & 31;
    int c = w & (NCH - 1);
    int rem = w >> 6;
    int o8 = rem % 15;
    int b = rem / 15;
    int d = o8 * 8 + (lane >> 2);
    int n0 = (lane & 3) * 4;
    float4 Al = __ldg((const float4*)(A_log + d * DS + n0));
    float An0 = -__expf(Al.x), An1 = -__expf(Al.y), An2 = -__expf(Al.z), An3 = -__expf(Al.w);
    size_t rbase = ((size_t)b * LSEQ + c * SCH);
    const float* dp = g_delta + rbase * DI + d;
    const float* up = g_u + rbase * DI + d;
    const float4* bp = (const float4*)(g_xdb + rbase * 36 + 4 + n0);
    float h0 = 0.f, h1 = 0.f, h2 = 0.f, h3 = 0.f;
    float P0 = 1.f, P1 = 1.f, P2 = 1.f, P3 = 1.f;
#pragma unroll 4
    for (int t = 0; t < SCH; t++) {
        float dlt = __ldg(dp);
        float uu = __ldg(up);
        float4 B4 = __ldg(bp);
        float e0 = __expf(dlt * An0), e1 = __expf(dlt * An1);
        float e2 = __expf(dlt * An2), e3 = __expf(dlt * An3);
        h0 = fmaf(e0, h0, uu * B4.x); P0 *= e0;
        h1 = fmaf(e1, h1, uu * B4.y); P1 *= e1;
        h2 = fmaf(e2, h2, uu * B4.z); P2 *= e2;
        h3 = fmaf(e3, h3, uu * B4.w); P3 *= e3;
        dp += DI; up += DI; bp += 9;
    }
    int o = ((c * BATCH + b) * DI + d) * DS + n0;
    *(float4*)(g_Hc + o) = make_float4(h0, h1, h2, h3);
    *(float4*)(g_P + o)  = make_float4(P0, P1, P2, P3);
}

__global__ void scan_phase2() {
    int tid = blockIdx.x * 256 + threadIdx.x;
    if (tid >= BATCH * DI * DS) return;
    float h = 0.f;
#pragma unroll
    for (int c = 0; c < NCH; c++) {
        int o = c * (BATCH * DI * DS) + tid;
        g_hinit[o] = h;
        h = fmaf(g_P[o], h, g_Hc[o]);
    }
}

__global__ __launch_bounds__(128) void scan_phase3(const float* __restrict__ A_log) {
    int w = blockIdx.x * 4 + (threadIdx.x >> 5);
    int lane = threadIdx.x & 31;
    int c = w & (NCH - 1);
    int rem = w >> 6;
    int o8 = rem % 15;
    int b = rem / 15;
    int d = o8 * 8 + (lane >> 2);
    int q = lane & 3;
    int n0 = q * 4;
    float4 Al = __ldg((const float4*)(A_log + d * DS + n0));
    float An0 = -__expf(Al.x), An1 = -__expf(Al.y), An2 = -__expf(Al.z), An3 = -__expf(Al.w);
    size_t rbase = ((size_t)b * LSEQ + c * SCH);
    const float* dp = g_delta + rbase * DI + d;
    const float* up = g_u + rbase * DI + d;
    const float4* bp = (const float4*)(g_xdb + rbase * 36 + 4 + n0);
    const float4* cp = (const float4*)(g_xdb + rbase * 36 + 20 + n0);
    float* yp = g_y + rbase * DI + d;
    int o = ((c * BATCH + b) * DI + d) * DS + n0;
    float4 hi = *(const float4*)(g_hinit + o);
    float h0 = hi.x, h1 = hi.y, h2 = hi.z, h3 = hi.w;
#pragma unroll 4
    for (int t = 0; t < SCH; t++) {
        float dlt = __ldg(dp);
        float uu = __ldg(up);
        float4 B4 = __ldg(bp);
        float4 C4 = __ldg(cp);
        float e0 = __expf(dlt * An0), e1 = __expf(dlt * An1);
        float e2 = __expf(dlt * An2), e3 = __expf(dlt * An3);
        h0 = fmaf(e0, h0, uu * B4.x);
        h1 = fmaf(e1, h1, uu * B4.y);
        h2 = fmaf(e2, h2, uu * B4.z);
        h3 = fmaf(e3, h3, uu * B4.w);
        float s = h0 * C4.x + h1 * C4.y + h2 * C4.z + h3 * C4.w;
        s += __shfl_xor_sync(0xffffffffu, s, 1);
        s += __shfl_xor_sync(0xffffffffu, s, 2);
        if (q == 0) yp[0] = s;
        dp += DI; up += DI; bp += 9; cp += 9; yp += DI;
    }
}

// ------------------------- 3x3 conv2d: halo-staged, single fill -------------------------
__global__ __launch_bounds__(256) void conv2d_res(const float* __restrict__ bias,
                                                  const float* __restrict__ x0,
                                                  float* __restrict__ outp) {
    __shared__ float Ah[3][66][60];   // 47520 bytes
    int p0 = blockIdx.x * 64;
    int tid = threadIdx.x;
    int l0 = p0 & (LSEQ - 1);
    int bI = p0 >> 14;
    int yy = l0 >> 7;
    int xb = l0 & 127;                // 0 or 64

    for (int i = tid; i < 3 * 66 * 60; i += 256) {
        int ry = i / (66 * 60);
        int rem = i - ry * (66 * 60);
        int px = rem / 60;
        int ci = rem - px * 60;
        int sy = yy + ry - 1;
        int sx = xb + px - 1;
        float v = 0.f;
        if ((unsigned)sy < 128u && (unsigned)sx < 128u)
            v = g_h[(size_t)((bI << 14) + (sy << 7) + sx) * DM + ci];
        Ah[ry][px][ci] = v;
    }
    __syncthreads();

    int r0 = (tid >> 4) * 4;          // pixel group
    int c0 = (tid & 15) * 4;          // out-channel group
    float acc[4][4];
#pragma unroll
    for (int i = 0; i < 4; i++)
#pragma unroll
        for (int j = 0; j < 4; j++) acc[i][j] = 0.f;

#pragma unroll
    for (int tap = 0; tap < 9; tap++) {
        int dy = tap / 3;             // 0..2 -> Ah row index directly
        int dx = tap % 3;             // 0..2 -> halo x offset directly
        const float* wrow = g_wT + tap * 3600;
#pragma unroll 6
        for (int k = 0; k < 60; k++) {
            float4 w4;
            if (c0 < 60) w4 = __ldg((const float4*)(wrow + k * 60 + c0));
            else         w4 = make_float4(0.f, 0.f, 0.f, 0.f);
            float a0 = Ah[dy][r0 + 0 + dx][k];
            float a1 = Ah[dy][r0 + 1 + dx][k];
            float a2 = Ah[dy][r0 + 2 + dx][k];
            float a3 = Ah[dy][r0 + 3 + dx][k];
            acc[0][0] = fmaf(a0, w4.x, acc[0][0]); acc[0][1] = fmaf(a0, w4.y, acc[0][1]);
            acc[0][2] = fmaf(a0, w4.z, acc[0][2]); acc[0][3] = fmaf(a0, w4.w, acc[0][3]);
            acc[1][0] = fmaf(a1, w4.x, acc[1][0]); acc[1][1] = fmaf(a1, w4.y, acc[1][1]);
            acc[1][2] = fmaf(a1, w4.z, acc[1][2]); acc[1][3] = fmaf(a1, w4.w, acc[1][3]);
            acc[2][0] = fmaf(a2, w4.x, acc[2][0]); acc[2][1] = fmaf(a2, w4.y, acc[2][1]);
            acc[2][2] = fmaf(a2, w4.z, acc[2][2]); acc[2][3] = fmaf(a2, w4.w, acc[2][3]);
            acc[3][0] = fmaf(a3, w4.x, acc[3][0]); acc[3][1] = fmaf(a3, w4.y, acc[3][1]);
            acc[3][2] = fmaf(a3, w4.z, acc[3][2]); acc[3][3] = fmaf(a3, w4.w, acc[3][3]);
        }
    }
#pragma unroll
    for (int i = 0; i < 4; i++) {
        int p = p0 + r0 + i;
#pragma unroll
        for (int j = 0; j < 4; j++) {
            int co = c0 + j;
            if (co < DM)
                outp[(size_t)p * DM + co] = acc[i][j] + bias[co] + x0[(size_t)p * DM + co];
        }
    }
}

// ------------------------- launch -------------------------
extern "C" void kernel_launch(void* const* d_in, const int* in_sizes, int n_in,
                              void* d_out, int out_size) {
    (void)in_sizes; (void)n_in; (void)out_size;
    const float* x         = (const float*)d_in[0];
    const float* ln_w      = (const float*)d_in[1];
    const float* ln_b      = (const float*)d_in[2];
    const float* in_proj_w = (const float*)d_in[3];
    const float* conv_w    = (const float*)d_in[4];
    const float* conv_b    = (const float*)d_in[5];
    const float* x_proj_w  = (const float*)d_in[6];
    const float* dt_proj_w = (const float*)d_in[7];
    const float* dt_proj_b = (const float*)d_in[8];
    const float* A_log     = (const float*)d_in[9];
    const float* Dv        = (const float*)d_in[10];
    const float* out_proj_w= (const float*)d_in[11];
    const float* conv2d_w  = (const float*)d_in[12];
    const float* conv2d_b  = (const float*)d_in[13];
    float* outp = (float*)d_out;

    float *p_hn, *p_xz, *p_xc, *p_h, *p_wti, *p_wtx, *p_wto;
    cudaGetSymbolAddress((void**)&p_hn,  g_hn);
    cudaGetSymbolAddress((void**)&p_xz,  g_xz);
    cudaGetSymbolAddress((void**)&p_xc,  g_xc);
    cudaGetSymbolAddress((void**)&p_h,   g_h);
    cudaGetSymbolAddress((void**)&p_wti, g_wt_in);
    cudaGetSymbolAddress((void**)&p_wtx, g_wt_xp);
    cudaGetSymbolAddress((void**)&p_wto, g_wt_out);

    prep_weights<<<dim3(132, 7), 256>>>(in_proj_w, x_proj_w, out_proj_w, conv2d_w);

    const float* hin = x;
    for (int layer = 0; layer < 2; layer++) {
        ln_kernel<<<BLR / 8, 256>>>(hin, ln_w + layer * DM, ln_b + layer * DM);
        gemm128<<<dim3(BLR / 128, 4), 256>>>(p_hn, p_wti + layer * 60 * 240,
                                             p_xz, 2 * DI, DM);
        conv1d_silu<<<(BLR * (DI / 4) + 255) / 256, 256>>>(conv_w + layer * DI * 4,
                                                           conv_b + layer * DI);
        gemm_xp<<<BLR / 128, 288>>>(p_xc, p_wtx + layer * 120 * 36);
        delta_kernel<<<(BLR * (DI / 4) + 255) / 256, 256>>>(dt_proj_w + layer * DI * 4,
                                                            dt_proj_b + layer * DI);
        scan_phase1<<<1920 / 4, 128>>>(A_log + layer * DI * DS);
        scan_phase2<<<15, 256>>>();
        scan_phase3<<<1920 / 4, 128>>>(A_log + layer * DI * DS);
        gemm_out_gated<<<BLR / 128, 256>>>(p_wto + layer * 120 * 60, Dv + layer * DI);
        hin = p_h;
    }
    conv2d_res<<<BLR / 64, 256>>>(conv2d_b, x, outp);
}

// round 7
// speedup vs baseline: 1.1253x; 1.1253x over previous
#include <cuda_runtime.h>

#define BATCH 2
#define LSEQ  16384
#define BLR   (BATCH*LSEQ)   // 32768 rows
#define DM    60
#define DI    120
#define DS    16
#define NCH   128
#define SCH   (LSEQ/NCH)     // 128

// ------------------------- scratch -------------------------
__device__ float g_hn[BLR*DM];
__device__ float g_xz[BLR*2*DI];
__device__ float g_xc[BLR*DI];
__device__ float g_xdb[BLR*36];
__device__ float g_delta[BLR*DI];
__device__ float g_u[BLR*DI];
__device__ float g_y[BLR*DI];
__device__ float g_h[BLR*DM];
__device__ float g_P [NCH*BATCH*DI*DS];
__device__ float g_Hc[NCH*BATCH*DI*DS];
__device__ float g_hinit[NCH*BATCH*DI*DS];
__device__ float g_wt_in [2*DM*2*DI];   // [60][240] per layer
__device__ float g_wt_xp [2*DI*36];     // [120][36]
__device__ float g_wt_out[2*DI*DM];     // [120][60]
__device__ float g_wT    [9*DM*DM];     // [tap][ci][co]

__device__ __forceinline__ float siluf(float x) { return x / (1.f + __expf(-x)); }

// ------------------------- weight prep -------------------------
__global__ void prep_weights(const float* __restrict__ in_w, const float* __restrict__ xp_w,
                             const float* __restrict__ out_w, const float* __restrict__ c2w) {
    int t = blockIdx.y;
    int i = blockIdx.x * 256 + threadIdx.x;
    if (t < 2) {
        if (i < 240 * 60) {
            int n = i / 60, k = i - n * 60;
            g_wt_in[t * 60 * 240 + k * 240 + n] = in_w[t * 240 * 60 + n * 60 + k];
        }
    } else if (t < 4) {
        int l = t - 2;
        if (i < 36 * 120) {
            int n = i / 120, k = i - n * 120;
            g_wt_xp[l * 120 * 36 + k * 36 + n] = xp_w[l * 36 * 120 + n * 120 + k];
        }
    } else if (t < 6) {
        int l = t - 4;
        if (i < 60 * 120) {
            int n = i / 120, k = i - n * 120;
            g_wt_out[l * 120 * 60 + k * 60 + n] = out_w[l * 60 * 120 + n * 120 + k];
        }
    } else {
        if (i < 9 * 60 * 60) {
            int tap = i / 3600;
            int r = i - tap * 3600;
            int ci = r / 60, co = r - ci * 60;
            g_wT[i] = c2w[(co * 60 + ci) * 9 + tap];
        }
    }
}

// ------------------------- LayerNorm (layer 0 only) -------------------------
__global__ void ln_kernel(const float* __restrict__ in, const float* __restrict__ w,
                          const float* __restrict__ b) {
    int row  = blockIdx.x * 8 + (threadIdx.x >> 5);
    int lane = threadIdx.x & 31;
    const float* r = in + (size_t)row * DM;
    float v0 = r[lane];
    float v1 = (lane + 32 < DM) ? r[lane + 32] : 0.f;
    float s = v0 + v1;
#pragma unroll
    for (int o = 16; o; o >>= 1) s += __shfl_xor_sync(0xffffffffu, s, o);
    float mu = s * (1.f / DM);
    float d0 = v0 - mu;
    float d1 = (lane + 32 < DM) ? (v1 - mu) : 0.f;
    float q = d0 * d0 + d1 * d1;
#pragma unroll
    for (int o = 16; o; o >>= 1) q += __shfl_xor_sync(0xffffffffu, q, o);
    float rstd = rsqrtf(q * (1.f / DM) + 1e-5f);
    float* op = g_hn + (size_t)row * DM;
    op[lane] = d0 * rstd * w[lane] + b[lane];
    if (lane + 32 < DM) op[lane + 32] = d1 * rstd * w[lane + 32] + b[lane + 32];
}

// ------------------------- GEMM 128x64, 8x4 microtile (in_proj) ---------------
__global__ __launch_bounds__(256) void gemm128(const float* __restrict__ A,
                                               const float* __restrict__ WT,
                                               float* __restrict__ C, int N, int K) {
    __shared__ float Asr[128][60];
    __shared__ float Ws[60][64];
    int m0 = blockIdx.x * 128;
    int n0 = blockIdx.y * 64;
    int tid = threadIdx.x;
    int r0 = (tid >> 4) * 8;
    int c0 = (tid & 15) * 4;
    float acc[8][4];
#pragma unroll
    for (int i = 0; i < 8; i++)
#pragma unroll
        for (int j = 0; j < 4; j++) acc[i][j] = 0.f;

    for (int kc = 0; kc < K; kc += 60) {
        for (int i = tid; i < 1920; i += 256) {
            int r = i / 15, kk = (i - r * 15) * 4;
            *(float4*)&Asr[r][kk] = *(const float4*)&A[(size_t)(m0 + r) * K + kc + kk];
        }
        for (int i = tid; i < 960; i += 256) {
            int k = i >> 4, n = (i & 15) * 4;
            int nn = n0 + n;
            float4 w;
            const float* wp = WT + (size_t)(kc + k) * N + nn;
            w.x = (nn + 0 < N) ? wp[0] : 0.f;
            w.y = (nn + 1 < N) ? wp[1] : 0.f;
            w.z = (nn + 2 < N) ? wp[2] : 0.f;
            w.w = (nn + 3 < N) ? wp[3] : 0.f;
            *(float4*)&Ws[k][n] = w;
        }
        __syncthreads();
#pragma unroll 6
        for (int k = 0; k < 60; k++) {
            float4 w4 = *(const float4*)&Ws[k][c0];
            float a[8];
#pragma unroll
            for (int i = 0; i < 8; i++) a[i] = Asr[r0 + i][k];
#pragma unroll
            for (int i = 0; i < 8; i++) {
                acc[i][0] = fmaf(a[i], w4.x, acc[i][0]);
                acc[i][1] = fmaf(a[i], w4.y, acc[i][1]);
                acc[i][2] = fmaf(a[i], w4.z, acc[i][2]);
                acc[i][3] = fmaf(a[i], w4.w, acc[i][3]);
            }
        }
        __syncthreads();
    }
#pragma unroll
    for (int i = 0; i < 8; i++) {
        int m = m0 + r0 + i;
        int nn = n0 + c0;
        *(float4*)&C[(size_t)m * N + nn] = make_float4(acc[i][0], acc[i][1], acc[i][2], acc[i][3]);
    }
}

// ------------------------- conv1d + SiLU -------------------------
__global__ void conv1d_silu(const float* __restrict__ cw, const float* __restrict__ cb) {
    int idx = blockIdx.x * 256 + threadIdx.x;
    if (idx >= BLR * (DI / 4)) return;
    int m = idx / (DI / 4);
    int d = (idx - m * (DI / 4)) * 4;
    int l = m & (LSEQ - 1);
    const float4* base = (const float4*)(g_xz + (size_t)m * (2 * DI) + d);
    float4 zero = make_float4(0.f, 0.f, 0.f, 0.f);
    float4 x0 = __ldg(base);
    float4 x1 = (l >= 1) ? __ldg(base - (2 * DI) / 4) : zero;
    float4 x2 = (l >= 2) ? __ldg(base - 2 * (2 * DI) / 4) : zero;
    float4 x3 = (l >= 3) ? __ldg(base - 3 * (2 * DI) / 4) : zero;
    float4 wa = __ldg((const float4*)(cw + (d + 0) * 4));
    float4 wb = __ldg((const float4*)(cw + (d + 1) * 4));
    float4 wc = __ldg((const float4*)(cw + (d + 2) * 4));
    float4 wd = __ldg((const float4*)(cw + (d + 3) * 4));
    float4 bb = __ldg((const float4*)(cb + d));
    float4 o;
    o.x = siluf(bb.x + x0.x * wa.w + x1.x * wa.z + x2.x * wa.y + x3.x * wa.x);
    o.y = siluf(bb.y + x0.y * wb.w + x1.y * wb.z + x2.y * wb.y + x3.y * wb.x);
    o.z = siluf(bb.z + x0.z * wc.w + x1.z * wc.z + x2.z * wc.y + x3.z * wc.x);
    o.w = siluf(bb.w + x0.w * wd.w + x1.w * wd.z + x2.w * wd.y + x3.w * wd.x);
    *(float4*)(g_xc + (size_t)m * DI + d) = o;
}

// ------------------------- x_proj GEMM 128x36 + fused delta/softplus epilogue ----
__global__ __launch_bounds__(288) void gemm_xp(const float* __restrict__ A,
                                               const float* __restrict__ WT,
                                               const float* __restrict__ dtw,
                                               const float* __restrict__ dtb) {
    __shared__ float Asr[128][60];
    __shared__ float Ws[60][36];
    __shared__ float sm_dt[128][4];
    int m0 = blockIdx.x * 128;
    int tid = threadIdx.x;
    int r0 = (tid / 9) * 4;
    int c0 = (tid % 9) * 4;
    float acc[4][4];
#pragma unroll
    for (int i = 0; i < 4; i++)
#pragma unroll
        for (int j = 0; j < 4; j++) acc[i][j] = 0.f;

    for (int kc = 0; kc < DI; kc += 60) {
        for (int i = tid; i < 1920; i += 288) {
            int r = i / 15, kk = (i - r * 15) * 4;
            *(float4*)&Asr[r][kk] = *(const float4*)&A[(size_t)(m0 + r) * DI + kc + kk];
        }
        for (int i = tid; i < 540; i += 288) {
            int k = i / 9, n = (i - k * 9) * 4;
            *(float4*)&Ws[k][n] = *(const float4*)&WT[(size_t)(kc + k) * 36 + n];
        }
        __syncthreads();
#pragma unroll 6
        for (int k = 0; k < 60; k++) {
            float4 w4 = *(const float4*)&Ws[k][c0];
            float a0 = Asr[r0 + 0][k], a1 = Asr[r0 + 1][k];
            float a2 = Asr[r0 + 2][k], a3 = Asr[r0 + 3][k];
            acc[0][0] = fmaf(a0, w4.x, acc[0][0]); acc[0][1] = fmaf(a0, w4.y, acc[0][1]);
            acc[0][2] = fmaf(a0, w4.z, acc[0][2]); acc[0][3] = fmaf(a0, w4.w, acc[0][3]);
            acc[1][0] = fmaf(a1, w4.x, acc[1][0]); acc[1][1] = fmaf(a1, w4.y, acc[1][1]);
            acc[1][2] = fmaf(a1, w4.z, acc[1][2]); acc[1][3] = fmaf(a1, w4.w, acc[1][3]);
            acc[2][0] = fmaf(a2, w4.x, acc[2][0]); acc[2][1] = fmaf(a2, w4.y, acc[2][1]);
            acc[2][2] = fmaf(a2, w4.z, acc[2][2]); acc[2][3] = fmaf(a2, w4.w, acc[2][3]);
            acc[3][0] = fmaf(a3, w4.x, acc[3][0]); acc[3][1] = fmaf(a3, w4.y, acc[3][1]);
            acc[3][2] = fmaf(a3, w4.z, acc[3][2]); acc[3][3] = fmaf(a3, w4.w, acc[3][3]);
        }
        __syncthreads();
    }
#pragma unroll
    for (int i = 0; i < 4; i++) {
        int m = m0 + r0 + i;
        *(float4*)&g_xdb[(size_t)m * 36 + c0] = make_float4(acc[i][0], acc[i][1], acc[i][2], acc[i][3]);
    }
    // stash dt columns (c0 == 0) in smem for the delta epilogue
    if (c0 == 0) {
#pragma unroll
        for (int i = 0; i < 4; i++)
            *(float4*)&sm_dt[r0 + i][0] = make_float4(acc[i][0], acc[i][1], acc[i][2], acc[i][3]);
    }
    __syncthreads();
    // delta = softplus(dt @ dtw^T + dtb); u = delta * xc
    for (int i = tid; i < 128 * DI; i += 288) {
        int r = i / DI;
        int d = i - r * DI;
        int m = m0 + r;
        float4 dt4 = *(const float4*)&sm_dt[r][0];
        float4 w4 = __ldg((const float4*)(dtw + d * 4));
        float s = __ldg(dtb + d) + dt4.x * w4.x + dt4.y * w4.y + dt4.z * w4.z + dt4.w * w4.w;
        float sp = (s > 20.f) ? s : log1pf(__expf(s));
        g_delta[(size_t)m * DI + d] = sp;
        g_u[(size_t)m * DI + d] = sp * g_xc[(size_t)m * DI + d];
    }
}

// ------------------------- chunked selective scan -------------------------
__global__ __launch_bounds__(128) void scan_phase1(const float* __restrict__ A_log) {
    int w = blockIdx.x * 4 + (threadIdx.x >> 5);
    int lane = threadIdx.x & 31;
    int c = w & (NCH - 1);
    int rem = w >> 7;                 // NCH = 128
    int o8 = rem % 15;
    int b = rem / 15;
    int d = o8 * 8 + (lane >> 2);
    int n0 = (lane & 3) * 4;
    float4 Al = __ldg((const float4*)(A_log + d * DS + n0));
    float An0 = -__expf(Al.x), An1 = -__expf(Al.y), An2 = -__expf(Al.z), An3 = -__expf(Al.w);
    size_t rbase = ((size_t)b * LSEQ + c * SCH);
    const float* dp = g_delta + rbase * DI + d;
    const float* up = g_u + rbase * DI + d;
    const float4* bp = (const float4*)(g_xdb + rbase * 36 + 4 + n0);
    float h0 = 0.f, h1 = 0.f, h2 = 0.f, h3 = 0.f;
    float P0 = 1.f, P1 = 1.f, P2 = 1.f, P3 = 1.f;
#pragma unroll 4
    for (int t = 0; t < SCH; t++) {
        float dlt = __ldg(dp);
        float uu = __ldg(up);
        float4 B4 = __ldg(bp);
        float e0 = __expf(dlt * An0), e1 = __expf(dlt * An1);
        float e2 = __expf(dlt * An2), e3 = __expf(dlt * An3);
        h0 = fmaf(e0, h0, uu * B4.x); P0 *= e0;
        h1 = fmaf(e1, h1, uu * B4.y); P1 *= e1;
        h2 = fmaf(e2, h2, uu * B4.z); P2 *= e2;
        h3 = fmaf(e3, h3, uu * B4.w); P3 *= e3;
        dp += DI; up += DI; bp += 9;
    }
    int o = ((c * BATCH + b) * DI + d) * DS + n0;
    *(float4*)(g_Hc + o) = make_float4(h0, h1, h2, h3);
    *(float4*)(g_P + o)  = make_float4(P0, P1, P2, P3);
}

__global__ void scan_phase2() {
    int tid = blockIdx.x * 256 + threadIdx.x;
    if (tid >= BATCH * DI * DS) return;
    float h = 0.f;
#pragma unroll 8
    for (int c = 0; c < NCH; c++) {
        int o = c * (BATCH * DI * DS) + tid;
        g_hinit[o] = h;
        h = fmaf(g_P[o], h, g_Hc[o]);
    }
}

__global__ __launch_bounds__(128) void scan_phase3(const float* __restrict__ A_log) {
    int w = blockIdx.x * 4 + (threadIdx.x >> 5);
    int lane = threadIdx.x & 31;
    int c = w & (NCH - 1);
    int rem = w >> 7;
    int o8 = rem % 15;
    int b = rem / 15;
    int d = o8 * 8 + (lane >> 2);
    int q = lane & 3;
    int n0 = q * 4;
    float4 Al = __ldg((const float4*)(A_log + d * DS + n0));
    float An0 = -__expf(Al.x), An1 = -__expf(Al.y), An2 = -__expf(Al.z), An3 = -__expf(Al.w);
    size_t rbase = ((size_t)b * LSEQ + c * SCH);
    const float* dp = g_delta + rbase * DI + d;
    const float* up = g_u + rbase * DI + d;
    const float4* bp = (const float4*)(g_xdb + rbase * 36 + 4 + n0);
    const float4* cp = (const float4*)(g_xdb + rbase * 36 + 20 + n0);
    float* yp = g_y + rbase * DI + d;
    int o = ((c * BATCH + b) * DI + d) * DS + n0;
    float4 hi = *(const float4*)(g_hinit + o);
    float h0 = hi.x, h1 = hi.y, h2 = hi.z, h3 = hi.w;
#pragma unroll 4
    for (int t = 0; t < SCH; t++) {
        float dlt = __ldg(dp);
        float uu = __ldg(up);
        float4 B4 = __ldg(bp);
        float4 C4 = __ldg(cp);
        float e0 = __expf(dlt * An0), e1 = __expf(dlt * An1);
        float e2 = __expf(dlt * An2), e3 = __expf(dlt * An3);
        h0 = fmaf(e0, h0, uu * B4.x);
        h1 = fmaf(e1, h1, uu * B4.y);
        h2 = fmaf(e2, h2, uu * B4.z);
        h3 = fmaf(e3, h3, uu * B4.w);
        float s = h0 * C4.x + h1 * C4.y + h2 * C4.z + h3 * C4.w;
        s += __shfl_xor_sync(0xffffffffu, s, 1);
        s += __shfl_xor_sync(0xffffffffu, s, 2);
        if (q == 0) yp[0] = s;
        dp += DI; up += DI; bp += 9; cp += 9; yp += DI;
    }
}

// ------------------------- out_proj 128x64, gated fill, optional fused LN -------
__global__ __launch_bounds__(256) void gemm_out_gated(const float* __restrict__ WT,
                                                      const float* __restrict__ Dvec,
                                                      const float* __restrict__ lnw,
                                                      const float* __restrict__ lnb,
                                                      int do_ln) {
    __shared__ float Asr[128][60];
    __shared__ float Ws[60][64];
    int m0 = blockIdx.x * 128;
    int tid = threadIdx.x;
    int r0 = (tid >> 4) * 8;
    int c0 = (tid & 15) * 4;
    float acc[8][4];
#pragma unroll
    for (int i = 0; i < 8; i++)
#pragma unroll
        for (int j = 0; j < 4; j++) acc[i][j] = 0.f;

    for (int kc = 0; kc < DI; kc += 60) {
        for (int i = tid; i < 128 * 60; i += 256) {
            int r = i / 60, k = i - r * 60;
            int m = m0 + r;
            int e = kc + k;
            float yv  = g_y [(size_t)m * DI + e];
            float xcv = g_xc[(size_t)m * DI + e];
            float zv  = g_xz[(size_t)m * (2 * DI) + DI + e];
            Asr[r][k] = (yv + __ldg(Dvec + e) * xcv) * siluf(zv);
        }
        for (int i = tid; i < 960; i += 256) {
            int k = i >> 4, n = (i & 15) * 4;
            float4 w;
            const float* wp = WT + (size_t)(kc + k) * DM + n;
            w.x = (n + 0 < DM) ? wp[0] : 0.f;
            w.y = (n + 1 < DM) ? wp[1] : 0.f;
            w.z = (n + 2 < DM) ? wp[2] : 0.f;
            w.w = (n + 3 < DM) ? wp[3] : 0.f;
            *(float4*)&Ws[k][n] = w;
        }
        __syncthreads();
#pragma unroll 6
        for (int k = 0; k < 60; k++) {
            float4 w4 = *(const float4*)&Ws[k][c0];
            float a[8];
#pragma unroll
            for (int i = 0; i < 8; i++) a[i] = Asr[r0 + i][k];
#pragma unroll
            for (int i = 0; i < 8; i++) {
                acc[i][0] = fmaf(a[i], w4.x, acc[i][0]);
                acc[i][1] = fmaf(a[i], w4.y, acc[i][1]);
                acc[i][2] = fmaf(a[i], w4.z, acc[i][2]);
                acc[i][3] = fmaf(a[i], w4.w, acc[i][3]);
            }
        }
        __syncthreads();
    }

    if (!do_ln) {
#pragma unroll
        for (int i = 0; i < 8; i++) {
            int m = m0 + r0 + i;
#pragma unroll
            for (int j = 0; j < 4; j++) {
                int n = c0 + j;
                if (n < DM) g_h[(size_t)m * DM + n] = acc[i][j];
            }
        }
        return;
    }
    // fused LayerNorm of the next layer: rows are complete across 16 lanes
    float4 w4 = make_float4(0.f, 0.f, 0.f, 0.f), b4 = w4;
    if (c0 < DM) {
        w4 = __ldg((const float4*)(lnw + c0));
        b4 = __ldg((const float4*)(lnb + c0));
    }
#pragma unroll
    for (int i = 0; i < 8; i++) {
        float s = acc[i][0] + acc[i][1] + acc[i][2] + acc[i][3];
        float q = acc[i][0]*acc[i][0] + acc[i][1]*acc[i][1] + acc[i][2]*acc[i][2] + acc[i][3]*acc[i][3];
        // reduce across the 16-lane column group (xor stays within the group)
        s += __shfl_xor_sync(0xffffffffu, s, 1);  q += __shfl_xor_sync(0xffffffffu, q, 1);
        s += __shfl_xor_sync(0xffffffffu, s, 2);  q += __shfl_xor_sync(0xffffffffu, q, 2);
        s += __shfl_xor_sync(0xffffffffu, s, 4);  q += __shfl_xor_sync(0xffffffffu, q, 4);
        s += __shfl_xor_sync(0xffffffffu, s, 8);  q += __shfl_xor_sync(0xffffffffu, q, 8);
        float mu = s * (1.f / DM);
        float var = q * (1.f / DM) - mu * mu;
        float rstd = rsqrtf(var + 1e-5f);
        int m = m0 + r0 + i;
        if (c0 < DM) {
            float4 o;
            o.x = (acc[i][0] - mu) * rstd * w4.x + b4.x;
            o.y = (acc[i][1] - mu) * rstd * w4.y + b4.y;
            o.z = (acc[i][2] - mu) * rstd * w4.z + b4.z;
            o.w = (acc[i][3] - mu) * rstd * w4.w + b4.w;
            *(float4*)&g_hn[(size_t)m * DM + c0] = o;
        }
    }
}

// ------------------------- 3x3 conv2d: halo-staged, single fill -------------------------
__global__ __launch_bounds__(256) void conv2d_res(const float* __restrict__ bias,
                                                  const float* __restrict__ x0,
                                                  float* __restrict__ outp) {
    __shared__ float Ah[3][66][60];
    int p0 = blockIdx.x * 64;
    int tid = threadIdx.x;
    int l0 = p0 & (LSEQ - 1);
    int bI = p0 >> 14;
    int yy = l0 >> 7;
    int xb = l0 & 127;

    for (int i = tid; i < 3 * 66 * 60; i += 256) {
        int ry = i / (66 * 60);
        int rem = i - ry * (66 * 60);
        int px = rem / 60;
        int ci = rem - px * 60;
        int sy = yy + ry - 1;
        int sx = xb + px - 1;
        float v = 0.f;
        if ((unsigned)sy < 128u && (unsigned)sx < 128u)
            v = g_h[(size_t)((bI << 14) + (sy << 7) + sx) * DM + ci];
        Ah[ry][px][ci] = v;
    }
    __syncthreads();

    int r0 = (tid >> 4) * 4;
    int c0 = (tid & 15) * 4;
    float acc[4][4];
#pragma unroll
    for (int i = 0; i < 4; i++)
#pragma unroll
        for (int j = 0; j < 4; j++) acc[i][j] = 0.f;

#pragma unroll
    for (int tap = 0; tap < 9; tap++) {
        int dy = tap / 3;
        int dx = tap % 3;
        const float* wrow = g_wT + tap * 3600;
#pragma unroll 6
        for (int k = 0; k < 60; k++) {
            float4 w4;
            if (c0 < 60) w4 = __ldg((const float4*)(wrow + k * 60 + c0));
            else         w4 = make_float4(0.f, 0.f, 0.f, 0.f);
            float a0 = Ah[dy][r0 + 0 + dx][k];
            float a1 = Ah[dy][r0 + 1 + dx][k];
            float a2 = Ah[dy][r0 + 2 + dx][k];
            float a3 = Ah[dy][r0 + 3 + dx][k];
            acc[0][0] = fmaf(a0, w4.x, acc[0][0]); acc[0][1] = fmaf(a0, w4.y, acc[0][1]);
            acc[0][2] = fmaf(a0, w4.z, acc[0][2]); acc[0][3] = fmaf(a0, w4.w, acc[0][3]);
            acc[1][0] = fmaf(a1, w4.x, acc[1][0]); acc[1][1] = fmaf(a1, w4.y, acc[1][1]);
            acc[1][2] = fmaf(a1, w4.z, acc[1][2]); acc[1][3] = fmaf(a1, w4.w, acc[1][3]);
            acc[2][0] = fmaf(a2, w4.x, acc[2][0]); acc[2][1] = fmaf(a2, w4.y, acc[2][1]);
            acc[2][2] = fmaf(a2, w4.z, acc[2][2]); acc[2][3] = fmaf(a2, w4.w, acc[2][3]);
            acc[3][0] = fmaf(a3, w4.x, acc[3][0]); acc[3][1] = fmaf(a3, w4.y, acc[3][1]);
            acc[3][2] = fmaf(a3, w4.z, acc[3][2]); acc[3][3] = fmaf(a3, w4.w, acc[3][3]);
        }
    }
#pragma unroll
    for (int i = 0; i < 4; i++) {
        int p = p0 + r0 + i;
#pragma unroll
        for (int j = 0; j < 4; j++) {
            int co = c0 + j;
            if (co < DM)
                outp[(size_t)p * DM + co] = acc[i][j] + bias[co] + x0[(size_t)p * DM + co];
        }
    }
}

// ------------------------- launch -------------------------
extern "C" void kernel_launch(void* const* d_in, const int* in_sizes, int n_in,
                              void* d_out, int out_size) {
    (void)in_sizes; (void)n_in; (void)out_size;
    const float* x         = (const float*)d_in[0];
    const float* ln_w      = (const float*)d_in[1];
    const float* ln_b      = (const float*)d_in[2];
    const float* in_proj_w = (const float*)d_in[3];
    const float* conv_w    = (const float*)d_in[4];
    const float* conv_b    = (const float*)d_in[5];
    const float* x_proj_w  = (const float*)d_in[6];
    const float* dt_proj_w = (const float*)d_in[7];
    const float* dt_proj_b = (const float*)d_in[8];
    const float* A_log     = (const float*)d_in[9];
    const float* Dv        = (const float*)d_in[10];
    const float* out_proj_w= (const float*)d_in[11];
    const float* conv2d_w  = (const float*)d_in[12];
    const float* conv2d_b  = (const float*)d_in[13];
    float* outp = (float*)d_out;

    float *p_hn, *p_xz, *p_xc, *p_wti, *p_wtx, *p_wto;
    cudaGetSymbolAddress((void**)&p_hn,  g_hn);
    cudaGetSymbolAddress((void**)&p_xz,  g_xz);
    cudaGetSymbolAddress((void**)&p_xc,  g_xc);
    cudaGetSymbolAddress((void**)&p_wti, g_wt_in);
    cudaGetSymbolAddress((void**)&p_wtx, g_wt_xp);
    cudaGetSymbolAddress((void**)&p_wto, g_wt_out);

    prep_weights<<<dim3(132, 7), 256>>>(in_proj_w, x_proj_w, out_proj_w, conv2d_w);
    ln_kernel<<<BLR / 8, 256>>>(x, ln_w, ln_b);

    int scan_blocks = (NCH * 15 * BATCH) / 4;   // 960
    for (int layer = 0; layer < 2; layer++) {
        gemm128<<<dim3(BLR / 128, 4), 256>>>(p_hn, p_wti + layer * 60 * 240,
                                             p_xz, 2 * DI, DM);
        conv1d_silu<<<(BLR * (DI / 4) + 255) / 256, 256>>>(conv_w + layer * DI * 4,
                                                           conv_b + layer * DI);
        gemm_xp<<<BLR / 128, 288>>>(p_xc, p_wtx + layer * 120 * 36,
                                    dt_proj_w + layer * DI * 4, dt_proj_b + layer * DI);
        scan_phase1<<<scan_blocks, 128>>>(A_log + layer * DI * DS);
        scan_phase2<<<15, 256>>>();
        scan_phase3<<<scan_blocks, 128>>>(A_log + layer * DI * DS);
        gemm_out_gated<<<BLR / 128, 256>>>(p_wto + layer * 120 * 60, Dv + layer * DI,
                                           ln_w + DM, ln_b + DM, layer == 0 ? 1 : 0);
    }
    conv2d_res<<<BLR / 64, 256>>>(conv2d_b, x, outp);
}

// round 8
// speedup vs baseline: 1.1999x; 1.0663x over previous
#include <cuda_runtime.h>

#define BATCH 2
#define LSEQ  16384
#define BLR   (BATCH*LSEQ)   // 32768 rows
#define DM    60
#define DI    120
#define DS    16
#define NCH   128
#define SCH   (LSEQ/NCH)     // 128

// ------------------------- scratch -------------------------
__device__ float g_hn[BLR*DM];
__device__ float g_xz[BLR*2*DI];
__device__ float g_xc[BLR*DI];
__device__ float g_xdb[BLR*36];
__device__ float g_delta[BLR*DI];
__device__ float g_u[BLR*DI];
__device__ float g_y[BLR*DI];
__device__ float g_h[BLR*DM];
__device__ float g_P [NCH*BATCH*DI*DS];
__device__ float g_Hc[NCH*BATCH*DI*DS];
__device__ float g_hinit[NCH*BATCH*DI*DS];
__device__ float g_wt_in [2*DM*2*DI];   // [60][240] per layer
__device__ float g_wt_xp [2*DI*36];     // [120][36]
__device__ float g_wt_out[2*DI*DM];     // [120][60]
__device__ float g_wT    [9*DM*DM];     // [tap][ci][co]

__device__ __forceinline__ float siluf(float x) { return x / (1.f + __expf(-x)); }

// ------------------------- packed f32x2 FMA helpers -------------------------
typedef unsigned long long u64;
__device__ __forceinline__ u64 ffma2(u64 a, u64 b, u64 c) {
    u64 d;
    asm("fma.rn.f32x2 %0, %1, %2, %3;" : "=l"(d) : "l"(a), "l"(b), "l"(c));
    return d;
}
__device__ __forceinline__ u64 pack2(float x) {
    u64 r;
    asm("mov.b64 %0, {%1, %1};" : "=l"(r) : "f"(x));
    return r;
}
__device__ __forceinline__ float2 unpack2(u64 v) {
    float2 f;
    asm("mov.b64 {%0, %1}, %2;" : "=f"(f.x), "=f"(f.y) : "l"(v));
    return f;
}

// ------------------------- weight prep -------------------------
__global__ void prep_weights(const float* __restrict__ in_w, const float* __restrict__ xp_w,
                             const float* __restrict__ out_w, const float* __restrict__ c2w) {
    int t = blockIdx.y;
    int i = blockIdx.x * 256 + threadIdx.x;
    if (t < 2) {
        if (i < 240 * 60) {
            int n = i / 60, k = i - n * 60;
            g_wt_in[t * 60 * 240 + k * 240 + n] = in_w[t * 240 * 60 + n * 60 + k];
        }
    } else if (t < 4) {
        int l = t - 2;
        if (i < 36 * 120) {
            int n = i / 120, k = i - n * 120;
            g_wt_xp[l * 120 * 36 + k * 36 + n] = xp_w[l * 36 * 120 + n * 120 + k];
        }
    } else if (t < 6) {
        int l = t - 4;
        if (i < 60 * 120) {
            int n = i / 120, k = i - n * 120;
            g_wt_out[l * 120 * 60 + k * 60 + n] = out_w[l * 60 * 120 + n * 120 + k];
        }
    } else {
        if (i < 9 * 60 * 60) {
            int tap = i / 3600;
            int r = i - tap * 3600;
            int ci = r / 60, co = r - ci * 60;
            g_wT[i] = c2w[(co * 60 + ci) * 9 + tap];
        }
    }
}

// ------------------------- LayerNorm (layer 0 only) -------------------------
__global__ void ln_kernel(const float* __restrict__ in, const float* __restrict__ w,
                          const float* __restrict__ b) {
    int row  = blockIdx.x * 8 + (threadIdx.x >> 5);
    int lane = threadIdx.x & 31;
    const float* r = in + (size_t)row * DM;
    float v0 = r[lane];
    float v1 = (lane + 32 < DM) ? r[lane + 32] : 0.f;
    float s = v0 + v1;
#pragma unroll
    for (int o = 16; o; o >>= 1) s += __shfl_xor_sync(0xffffffffu, s, o);
    float mu = s * (1.f / DM);
    float d0 = v0 - mu;
    float d1 = (lane + 32 < DM) ? (v1 - mu) : 0.f;
    float q = d0 * d0 + d1 * d1;
#pragma unroll
    for (int o = 16; o; o >>= 1) q += __shfl_xor_sync(0xffffffffu, q, o);
    float rstd = rsqrtf(q * (1.f / DM) + 1e-5f);
    float* op = g_hn + (size_t)row * DM;
    op[lane] = d0 * rstd * w[lane] + b[lane];
    if (lane + 32 < DM) op[lane + 32] = d1 * rstd * w[lane + 32] + b[lane + 32];
}

// ------------------------- GEMM 128x64, 8x4 microtile, f32x2 (in_proj) --------
__global__ __launch_bounds__(256) void gemm128(const float* __restrict__ A,
                                               const float* __restrict__ WT,
                                               float* __restrict__ C, int N, int K) {
    __shared__ float Asr[128][60];
    __shared__ float Ws[60][64];
    int m0 = blockIdx.x * 128;
    int n0 = blockIdx.y * 64;
    int tid = threadIdx.x;
    int r0 = (tid >> 4) * 8;
    int c0 = (tid & 15) * 4;
    u64 acc2[8][2];
#pragma unroll
    for (int i = 0; i < 8; i++) { acc2[i][0] = 0ull; acc2[i][1] = 0ull; }

    for (int kc = 0; kc < K; kc += 60) {
        for (int i = tid; i < 1920; i += 256) {
            int r = i / 15, kk = (i - r * 15) * 4;
            *(float4*)&Asr[r][kk] = *(const float4*)&A[(size_t)(m0 + r) * K + kc + kk];
        }
        for (int i = tid; i < 960; i += 256) {
            int k = i >> 4, n = (i & 15) * 4;
            int nn = n0 + n;
            float4 w;
            const float* wp = WT + (size_t)(kc + k) * N + nn;
            w.x = (nn + 0 < N) ? wp[0] : 0.f;
            w.y = (nn + 1 < N) ? wp[1] : 0.f;
            w.z = (nn + 2 < N) ? wp[2] : 0.f;
            w.w = (nn + 3 < N) ? wp[3] : 0.f;
            *(float4*)&Ws[k][n] = w;
        }
        __syncthreads();
#pragma unroll 6
        for (int k = 0; k < 60; k++) {
            ulonglong2 w2 = *(const ulonglong2*)&Ws[k][c0];
#pragma unroll
            for (int i = 0; i < 8; i++) {
                u64 ap = pack2(Asr[r0 + i][k]);
                acc2[i][0] = ffma2(ap, w2.x, acc2[i][0]);
                acc2[i][1] = ffma2(ap, w2.y, acc2[i][1]);
            }
        }
        __syncthreads();
    }
#pragma unroll
    for (int i = 0; i < 8; i++) {
        int m = m0 + r0 + i;
        int nn = n0 + c0;
        float2 p0 = unpack2(acc2[i][0]);
        float2 p1 = unpack2(acc2[i][1]);
        *(float4*)&C[(size_t)m * N + nn] = make_float4(p0.x, p0.y, p1.x, p1.y);
    }
}

// ------------------------- conv1d + SiLU -------------------------
__global__ void conv1d_silu(const float* __restrict__ cw, const float* __restrict__ cb) {
    int idx = blockIdx.x * 256 + threadIdx.x;
    if (idx >= BLR * (DI / 4)) return;
    int m = idx / (DI / 4);
    int d = (idx - m * (DI / 4)) * 4;
    int l = m & (LSEQ - 1);
    const float4* base = (const float4*)(g_xz + (size_t)m * (2 * DI) + d);
    float4 zero = make_float4(0.f, 0.f, 0.f, 0.f);
    float4 x0 = __ldg(base);
    float4 x1 = (l >= 1) ? __ldg(base - (2 * DI) / 4) : zero;
    float4 x2 = (l >= 2) ? __ldg(base - 2 * (2 * DI) / 4) : zero;
    float4 x3 = (l >= 3) ? __ldg(base - 3 * (2 * DI) / 4) : zero;
    float4 wa = __ldg((const float4*)(cw + (d + 0) * 4));
    float4 wb = __ldg((const float4*)(cw + (d + 1) * 4));
    float4 wc = __ldg((const float4*)(cw + (d + 2) * 4));
    float4 wd = __ldg((const float4*)(cw + (d + 3) * 4));
    float4 bb = __ldg((const float4*)(cb + d));
    float4 o;
    o.x = siluf(bb.x + x0.x * wa.w + x1.x * wa.z + x2.x * wa.y + x3.x * wa.x);
    o.y = siluf(bb.y + x0.y * wb.w + x1.y * wb.z + x2.y * wb.y + x3.y * wb.x);
    o.z = siluf(bb.z + x0.z * wc.w + x1.z * wc.z + x2.z * wc.y + x3.z * wc.x);
    o.w = siluf(bb.w + x0.w * wd.w + x1.w * wd.z + x2.w * wd.y + x3.w * wd.x);
    *(float4*)(g_xc + (size_t)m * DI + d) = o;
}

// ------------------------- x_proj GEMM 128x36 + fused delta epilogue, f32x2 ----
__global__ __launch_bounds__(288) void gemm_xp(const float* __restrict__ A,
                                               const float* __restrict__ WT,
                                               const float* __restrict__ dtw,
                                               const float* __restrict__ dtb) {
    __shared__ float Asr[128][60];
    __shared__ float Ws[60][36];
    __shared__ float sm_dt[128][4];
    int m0 = blockIdx.x * 128;
    int tid = threadIdx.x;
    int r0 = (tid / 9) * 4;
    int c0 = (tid % 9) * 4;
    u64 acc2[4][2];
#pragma unroll
    for (int i = 0; i < 4; i++) { acc2[i][0] = 0ull; acc2[i][1] = 0ull; }

    for (int kc = 0; kc < DI; kc += 60) {
        for (int i = tid; i < 1920; i += 288) {
            int r = i / 15, kk = (i - r * 15) * 4;
            *(float4*)&Asr[r][kk] = *(const float4*)&A[(size_t)(m0 + r) * DI + kc + kk];
        }
        for (int i = tid; i < 540; i += 288) {
            int k = i / 9, n = (i - k * 9) * 4;
            *(float4*)&Ws[k][n] = *(const float4*)&WT[(size_t)(kc + k) * 36 + n];
        }
        __syncthreads();
#pragma unroll 6
        for (int k = 0; k < 60; k++) {
            ulonglong2 w2 = *(const ulonglong2*)&Ws[k][c0];
#pragma unroll
            for (int i = 0; i < 4; i++) {
                u64 ap = pack2(Asr[r0 + i][k]);
                acc2[i][0] = ffma2(ap, w2.x, acc2[i][0]);
                acc2[i][1] = ffma2(ap, w2.y, acc2[i][1]);
            }
        }
        __syncthreads();
    }
    float accf[4][4];
#pragma unroll
    for (int i = 0; i < 4; i++) {
        float2 p0 = unpack2(acc2[i][0]);
        float2 p1 = unpack2(acc2[i][1]);
        accf[i][0] = p0.x; accf[i][1] = p0.y; accf[i][2] = p1.x; accf[i][3] = p1.y;
    }
#pragma unroll
    for (int i = 0; i < 4; i++) {
        int m = m0 + r0 + i;
        *(float4*)&g_xdb[(size_t)m * 36 + c0] = make_float4(accf[i][0], accf[i][1], accf[i][2], accf[i][3]);
    }
    if (c0 == 0) {
#pragma unroll
        for (int i = 0; i < 4; i++)
            *(float4*)&sm_dt[r0 + i][0] = make_float4(accf[i][0], accf[i][1], accf[i][2], accf[i][3]);
    }
    __syncthreads();
    for (int i = tid; i < 128 * DI; i += 288) {
        int r = i / DI;
        int d = i - r * DI;
        int m = m0 + r;
        float4 dt4 = *(const float4*)&sm_dt[r][0];
        float4 w4 = __ldg((const float4*)(dtw + d * 4));
        float s = __ldg(dtb + d) + dt4.x * w4.x + dt4.y * w4.y + dt4.z * w4.z + dt4.w * w4.w;
        float sp = (s > 20.f) ? s : log1pf(__expf(s));
        g_delta[(size_t)m * DI + d] = sp;
        g_u[(size_t)m * DI + d] = sp * g_xc[(size_t)m * DI + d];
    }
}

// ------------------------- chunked selective scan -------------------------
__global__ __launch_bounds__(128) void scan_phase1(const float* __restrict__ A_log) {
    int w = blockIdx.x * 4 + (threadIdx.x >> 5);
    int lane = threadIdx.x & 31;
    int c = w & (NCH - 1);
    int rem = w >> 7;
    int o8 = rem % 15;
    int b = rem / 15;
    int d = o8 * 8 + (lane >> 2);
    int n0 = (lane & 3) * 4;
    float4 Al = __ldg((const float4*)(A_log + d * DS + n0));
    float An0 = -__expf(Al.x), An1 = -__expf(Al.y), An2 = -__expf(Al.z), An3 = -__expf(Al.w);
    size_t rbase = ((size_t)b * LSEQ + c * SCH);
    const float* dp = g_delta + rbase * DI + d;
    const float* up = g_u + rbase * DI + d;
    const float4* bp = (const float4*)(g_xdb + rbase * 36 + 4 + n0);
    float h0 = 0.f, h1 = 0.f, h2 = 0.f, h3 = 0.f;
    float P0 = 1.f, P1 = 1.f, P2 = 1.f, P3 = 1.f;
#pragma unroll 4
    for (int t = 0; t < SCH; t++) {
        float dlt = __ldg(dp);
        float uu = __ldg(up);
        float4 B4 = __ldg(bp);
        float e0 = __expf(dlt * An0), e1 = __expf(dlt * An1);
        float e2 = __expf(dlt * An2), e3 = __expf(dlt * An3);
        h0 = fmaf(e0, h0, uu * B4.x); P0 *= e0;
        h1 = fmaf(e1, h1, uu * B4.y); P1 *= e1;
        h2 = fmaf(e2, h2, uu * B4.z); P2 *= e2;
        h3 = fmaf(e3, h3, uu * B4.w); P3 *= e3;
        dp += DI; up += DI; bp += 9;
    }
    int o = ((c * BATCH + b) * DI + d) * DS + n0;
    *(float4*)(g_Hc + o) = make_float4(h0, h1, h2, h3);
    *(float4*)(g_P + o)  = make_float4(P0, P1, P2, P3);
}

__global__ void scan_phase2() {
    int tid = blockIdx.x * 256 + threadIdx.x;
    if (tid >= BATCH * DI * DS) return;
    float h = 0.f;
#pragma unroll 8
    for (int c = 0; c < NCH; c++) {
        int o = c * (BATCH * DI * DS) + tid;
        g_hinit[o] = h;
        h = fmaf(g_P[o], h, g_Hc[o]);
    }
}

__global__ __launch_bounds__(128) void scan_phase3(const float* __restrict__ A_log) {
    int w = blockIdx.x * 4 + (threadIdx.x >> 5);
    int lane = threadIdx.x & 31;
    int c = w & (NCH - 1);
    int rem = w >> 7;
    int o8 = rem % 15;
    int b = rem / 15;
    int d = o8 * 8 + (lane >> 2);
    int q = lane & 3;
    int n0 = q * 4;
    float4 Al = __ldg((const float4*)(A_log + d * DS + n0));
    float An0 = -__expf(Al.x), An1 = -__expf(Al.y), An2 = -__expf(Al.z), An3 = -__expf(Al.w);
    size_t rbase = ((size_t)b * LSEQ + c * SCH);
    const float* dp = g_delta + rbase * DI + d;
    const float* up = g_u + rbase * DI + d;
    const float4* bp = (const float4*)(g_xdb + rbase * 36 + 4 + n0);
    const float4* cp = (const float4*)(g_xdb + rbase * 36 + 20 + n0);
    float* yp = g_y + rbase * DI + d;
    int o = ((c * BATCH + b) * DI + d) * DS + n0;
    float4 hi = *(const float4*)(g_hinit + o);
    float h0 = hi.x, h1 = hi.y, h2 = hi.z, h3 = hi.w;
#pragma unroll 4
    for (int t = 0; t < SCH; t++) {
        float dlt = __ldg(dp);
        float uu = __ldg(up);
        float4 B4 = __ldg(bp);
        float4 C4 = __ldg(cp);
        float e0 = __expf(dlt * An0), e1 = __expf(dlt * An1);
        float e2 = __expf(dlt * An2), e3 = __expf(dlt * An3);
        h0 = fmaf(e0, h0, uu * B4.x);
        h1 = fmaf(e1, h1, uu * B4.y);
        h2 = fmaf(e2, h2, uu * B4.z);
        h3 = fmaf(e3, h3, uu * B4.w);
        float s = h0 * C4.x + h1 * C4.y + h2 * C4.z + h3 * C4.w;
        s += __shfl_xor_sync(0xffffffffu, s, 1);
        s += __shfl_xor_sync(0xffffffffu, s, 2);
        if (q == 0) yp[0] = s;
        dp += DI; up += DI; bp += 9; cp += 9; yp += DI;
    }
}

// ------------------------- out_proj 128x64 gated, f32x2, optional fused LN -------
__global__ __launch_bounds__(256) void gemm_out_gated(const float* __restrict__ WT,
                                                      const float* __restrict__ Dvec,
                                                      const float* __restrict__ lnw,
                                                      const float* __restrict__ lnb,
                                                      int do_ln) {
    __shared__ float Asr[128][60];
    __shared__ float Ws[60][64];
    int m0 = blockIdx.x * 128;
    int tid = threadIdx.x;
    int r0 = (tid >> 4) * 8;
    int c0 = (tid & 15) * 4;
    u64 acc2[8][2];
#pragma unroll
    for (int i = 0; i < 8; i++) { acc2[i][0] = 0ull; acc2[i][1] = 0ull; }

    for (int kc = 0; kc < DI; kc += 60) {
        for (int i = tid; i < 128 * 60; i += 256) {
            int r = i / 60, k = i - r * 60;
            int m = m0 + r;
            int e = kc + k;
            float yv  = g_y [(size_t)m * DI + e];
            float xcv = g_xc[(size_t)m * DI + e];
            float zv  = g_xz[(size_t)m * (2 * DI) + DI + e];
            Asr[r][k] = (yv + __ldg(Dvec + e) * xcv) * siluf(zv);
        }
        for (int i = tid; i < 960; i += 256) {
            int k = i >> 4, n = (i & 15) * 4;
            float4 w;
            const float* wp = WT + (size_t)(kc + k) * DM + n;
            w.x = (n + 0 < DM) ? wp[0] : 0.f;
            w.y = (n + 1 < DM) ? wp[1] : 0.f;
            w.z = (n + 2 < DM) ? wp[2] : 0.f;
            w.w = (n + 3 < DM) ? wp[3] : 0.f;
            *(float4*)&Ws[k][n] = w;
        }
        __syncthreads();
#pragma unroll 6
        for (int k = 0; k < 60; k++) {
            ulonglong2 w2 = *(const ulonglong2*)&Ws[k][c0];
#pragma unroll
            for (int i = 0; i < 8; i++) {
                u64 ap = pack2(Asr[r0 + i][k]);
                acc2[i][0] = ffma2(ap, w2.x, acc2[i][0]);
                acc2[i][1] = ffma2(ap, w2.y, acc2[i][1]);
            }
        }
        __syncthreads();
    }
    float acc[8][4];
#pragma unroll
    for (int i = 0; i < 8; i++) {
        float2 p0 = unpack2(acc2[i][0]);
        float2 p1 = unpack2(acc2[i][1]);
        acc[i][0] = p0.x; acc[i][1] = p0.y; acc[i][2] = p1.x; acc[i][3] = p1.y;
    }

    if (!do_ln) {
#pragma unroll
        for (int i = 0; i < 8; i++) {
            int m = m0 + r0 + i;
#pragma unroll
            for (int j = 0; j < 4; j++) {
                int n = c0 + j;
                if (n < DM) g_h[(size_t)m * DM + n] = acc[i][j];
            }
        }
        return;
    }
    float4 w4 = make_float4(0.f, 0.f, 0.f, 0.f), b4 = w4;
    if (c0 < DM) {
        w4 = __ldg((const float4*)(lnw + c0));
        b4 = __ldg((const float4*)(lnb + c0));
    }
#pragma unroll
    for (int i = 0; i < 8; i++) {
        float s = acc[i][0] + acc[i][1] + acc[i][2] + acc[i][3];
        float q = acc[i][0]*acc[i][0] + acc[i][1]*acc[i][1] + acc[i][2]*acc[i][2] + acc[i][3]*acc[i][3];
        s += __shfl_xor_sync(0xffffffffu, s, 1);  q += __shfl_xor_sync(0xffffffffu, q, 1);
        s += __shfl_xor_sync(0xffffffffu, s, 2);  q += __shfl_xor_sync(0xffffffffu, q, 2);
        s += __shfl_xor_sync(0xffffffffu, s, 4);  q += __shfl_xor_sync(0xffffffffu, q, 4);
        s += __shfl_xor_sync(0xffffffffu, s, 8);  q += __shfl_xor_sync(0xffffffffu, q, 8);
        float mu = s * (1.f / DM);
        float var = q * (1.f / DM) - mu * mu;
        float rstd = rsqrtf(var + 1e-5f);
        int m = m0 + r0 + i;
        if (c0 < DM) {
            float4 o;
            o.x = (acc[i][0] - mu) * rstd * w4.x + b4.x;
            o.y = (acc[i][1] - mu) * rstd * w4.y + b4.y;
            o.z = (acc[i][2] - mu) * rstd * w4.z + b4.z;
            o.w = (acc[i][3] - mu) * rstd * w4.w + b4.w;
            *(float4*)&g_hn[(size_t)m * DM + c0] = o;
        }
    }
}

// ------------------------- 3x3 conv2d: halo-staged, f32x2 -------------------------
__global__ __launch_bounds__(256) void conv2d_res(const float* __restrict__ bias,
                                                  const float* __restrict__ x0,
                                                  float* __restrict__ outp) {
    __shared__ float Ah[3][66][60];
    int p0 = blockIdx.x * 64;
    int tid = threadIdx.x;
    int l0 = p0 & (LSEQ - 1);
    int bI = p0 >> 14;
    int yy = l0 >> 7;
    int xb = l0 & 127;

    for (int i = tid; i < 3 * 66 * 60; i += 256) {
        int ry = i / (66 * 60);
        int rem = i - ry * (66 * 60);
        int px = rem / 60;
        int ci = rem - px * 60;
        int sy = yy + ry - 1;
        int sx = xb + px - 1;
        float v = 0.f;
        if ((unsigned)sy < 128u && (unsigned)sx < 128u)
            v = g_h[(size_t)((bI << 14) + (sy << 7) + sx) * DM + ci];
        Ah[ry][px][ci] = v;
    }
    __syncthreads();

    int r0 = (tid >> 4) * 4;
    int c0 = (tid & 15) * 4;
    u64 acc2[4][2];
#pragma unroll
    for (int i = 0; i < 4; i++) { acc2[i][0] = 0ull; acc2[i][1] = 0ull; }

#pragma unroll
    for (int tap = 0; tap < 9; tap++) {
        int dy = tap / 3;
        int dx = tap % 3;
        const float* wrow = g_wT + tap * 3600;
#pragma unroll 6
        for (int k = 0; k < 60; k++) {
            ulonglong2 w2;
            if (c0 < 60) w2 = __ldg((const ulonglong2*)(wrow + k * 60 + c0));
            else         { w2.x = 0ull; w2.y = 0ull; }
            u64 a0 = pack2(Ah[dy][r0 + 0 + dx][k]);
            u64 a1 = pack2(Ah[dy][r0 + 1 + dx][k]);
            u64 a2 = pack2(Ah[dy][r0 + 2 + dx][k]);
            u64 a3 = pack2(Ah[dy][r0 + 3 + dx][k]);
            acc2[0][0] = ffma2(a0, w2.x, acc2[0][0]); acc2[0][1] = ffma2(a0, w2.y, acc2[0][1]);
            acc2[1][0] = ffma2(a1, w2.x, acc2[1][0]); acc2[1][1] = ffma2(a1, w2.y, acc2[1][1]);
            acc2[2][0] = ffma2(a2, w2.x, acc2[2][0]); acc2[2][1] = ffma2(a2, w2.y, acc2[2][1]);
            acc2[3][0] = ffma2(a3, w2.x, acc2[3][0]); acc2[3][1] = ffma2(a3, w2.y, acc2[3][1]);
        }
    }
#pragma unroll
    for (int i = 0; i < 4; i++) {
        int p = p0 + r0 + i;
        float2 q0 = unpack2(acc2[i][0]);
        float2 q1 = unpack2(acc2[i][1]);
        float av[4] = {q0.x, q0.y, q1.x, q1.y};
#pragma unroll
        for (int j = 0; j < 4; j++) {
            int co = c0 + j;
            if (co < DM)
                outp[(size_t)p * DM + co] = av[j] + bias[co] + x0[(size_t)p * DM + co];
        }
    }
}

// ------------------------- launch -------------------------
extern "C" void kernel_launch(void* const* d_in, const int* in_sizes, int n_in,
                              void* d_out, int out_size) {
    (void)in_sizes; (void)n_in; (void)out_size;
    const float* x         = (const float*)d_in[0];
    const float* ln_w      = (const float*)d_in[1];
    const float* ln_b      = (const float*)d_in[2];
    const float* in_proj_w = (const float*)d_in[3];
    const float* conv_w    = (const float*)d_in[4];
    const float* conv_b    = (const float*)d_in[5];
    const float* x_proj_w  = (const float*)d_in[6];
    const float* dt_proj_w = (const float*)d_in[7];
    const float* dt_proj_b = (const float*)d_in[8];
    const float* A_log     = (const float*)d_in[9];
    const float* Dv        = (const float*)d_in[10];
    const float* out_proj_w= (const float*)d_in[11];
    const float* conv2d_w  = (const float*)d_in[12];
    const float* conv2d_b  = (const float*)d_in[13];
    float* outp = (float*)d_out;

    float *p_hn, *p_xz, *p_xc, *p_wti, *p_wtx, *p_wto;
    cudaGetSymbolAddress((void**)&p_hn,  g_hn);
    cudaGetSymbolAddress((void**)&p_xz,  g_xz);
    cudaGetSymbolAddress((void**)&p_xc,  g_xc);
    cudaGetSymbolAddress((void**)&p_wti, g_wt_in);
    cudaGetSymbolAddress((void**)&p_wtx, g_wt_xp);
    cudaGetSymbolAddress((void**)&p_wto, g_wt_out);

    prep_weights<<<dim3(132, 7), 256>>>(in_proj_w, x_proj_w, out_proj_w, conv2d_w);
    ln_kernel<<<BLR / 8, 256>>>(x, ln_w, ln_b);

    int scan_blocks = (NCH * 15 * BATCH) / 4;   // 960
    for (int layer = 0; layer < 2; layer++) {
        gemm128<<<dim3(BLR / 128, 4), 256>>>(p_hn, p_wti + layer * 60 * 240,
                                             p_xz, 2 * DI, DM);
        conv1d_silu<<<(BLR * (DI / 4) + 255) / 256, 256>>>(conv_w + layer * DI * 4,
                                                           conv_b + layer * DI);
        gemm_xp<<<BLR / 128, 288>>>(p_xc, p_wtx + layer * 120 * 36,
                                    dt_proj_w + layer * DI * 4, dt_proj_b + layer * DI);
        scan_phase1<<<scan_blocks, 128>>>(A_log + layer * DI * DS);
        scan_phase2<<<15, 256>>>();
        scan_phase3<<<scan_blocks, 128>>>(A_log + layer * DI * DS);
        gemm_out_gated<<<BLR / 128, 256>>>(p_wto + layer * 120 * 60, Dv + layer * DI,
                                           ln_w + DM, ln_b + DM, layer == 0 ? 1 : 0);
    }
    conv2d_res<<<BLR / 64, 256>>>(conv2d_b, x, outp);
}